// round 4
// baseline (speedup 1.0000x reference)
#include <cuda_runtime.h>
#include <math.h>

#define B_    128
#define H_    512
#define W_    512
#define P_    64
#define DEPTH_ 4
#define EPS_  1e-5f

// ---------------- scratch (__device__ globals; no runtime allocation) ----------------
// TJ[b][h][n]: n in [0,256) = x @ o_rel_xj (d*64+p), n in [256,512) = x @ o_xj
// TI[b][w][n]: same with xt @ o_rel_xi / o_xi
__device__ float g_TJ[(size_t)B_ * 512 * 512];
__device__ float g_TI[(size_t)B_ * 512 * 512];
__device__ float g_Wrow[512 * 512];
__device__ float g_Wcol[512 * 512];
__device__ float g_PT[(size_t)2 * B_ * DEPTH_ * 64 * 64];  // [side][b][d][p][q]
__device__ float g_orel[(size_t)2 * B_ * DEPTH_ * 64];     // [side][b][d][p]
__device__ float g_stats[B_ * 2];                          // mean*scale, std*scale

// ---------------- packed f32x2 helpers ----------------
__device__ __forceinline__ unsigned long long pack2(float x) {
    unsigned long long r;
    asm("mov.b64 %0, {%1, %1};" : "=l"(r) : "f"(x));
    return r;
}
__device__ __forceinline__ void ffma2(unsigned long long &acc, unsigned long long a,
                                      unsigned long long b) {
    asm("fma.rn.f32x2 %0, %1, %2, %0;" : "+l"(acc) : "l"(a), "l"(b));
}

// ---------------- K0a: assemble combined weights ----------------
__global__ void k_prep(const float* __restrict__ o_xj, const float* __restrict__ o_xi,
                       const float* __restrict__ orel_xj, const float* __restrict__ orel_xi) {
    int idx = blockIdx.x * blockDim.x + threadIdx.x;   // 0 .. 2*262144-1
    int which = idx >> 18;
    int e = idx & 262143;
    int k = e >> 9, n = e & 511;
    int rel = (n < 256);
    int d = (n & 255) >> 6;
    int p = n & 63;
    float val;
    if (which == 0) val = (rel ? orel_xj : o_xj)[(d * 512 + k) * 64 + p];
    else            val = (rel ? orel_xi : o_xi)[(d * 512 + k) * 64 + p];
    (which == 0 ? g_Wrow : g_Wcol)[k * 512 + n] = val;
}

// ---------------- K0b: per-batch mean/std of x (scaled) ----------------
__global__ void k_stats(const float* __restrict__ x) {
    int b = blockIdx.x, tid = threadIdx.x;
    const float* xb = x + (size_t)b * H_ * W_;
    float s = 0.f, ss = 0.f;
    for (int i = tid; i < H_ * W_; i += 256) {
        float v = xb[i];
        s += v; ss += v * v;
    }
    __shared__ float r1[256], r2[256];
    r1[tid] = s; r2[tid] = ss; __syncthreads();
    for (int st = 128; st > 0; st >>= 1) {
        if (tid < st) { r1[tid] += r1[tid + st]; r2[tid] += r2[tid + st]; }
        __syncthreads();
    }
    if (tid == 0) {
        float n = (float)(H_ * W_);
        float mean = r1[0] / n;
        float var = (r2[0] - n * mean * mean) / (n - 1.f);
        float scale = ((float)H_ / P_) * ((float)W_ / P_);   // 64
        g_stats[b * 2 + 0] = mean * scale;
        g_stats[b * 2 + 1] = sqrtf(var) * scale;
    }
}

// ---------------- K1: big batched GEMM, 128x128 tile, 8x8 micro (f32x2) ----------------
// side 0: C[h][n] = sum_w x[b][h][w] * Wrow[w][n]   (A transposed-in-k loads)
// side 1: C[w][n] = sum_h x[b][h][w] * Wcol[h][n]
__global__ __launch_bounds__(256) void k_bigmm(const float* __restrict__ x) {
    const int side = blockIdx.z & 1;
    const int b = blockIdx.z >> 1;
    const int m0 = blockIdx.y * 128;
    const int n0 = blockIdx.x * 128;
    const float* A = x + (size_t)b * (H_ * W_);
    const float* Wg = side ? g_Wcol : g_Wrow;
    float* Cg = (side ? g_TI : g_TJ) + (size_t)b * (512 * 512);

    __shared__ __align__(16) float As[16][132];
    __shared__ __align__(16) float Bs[16][132];

    const int tid = threadIdx.x;
    const int trow = tid >> 4, tcol = tid & 15;
    const int mt = trow * 8, nt = tcol * 8;

    unsigned long long acc[8][4];
#pragma unroll
    for (int i = 0; i < 8; i++)
#pragma unroll
        for (int j = 0; j < 4; j++) acc[i][j] = 0ull;

    for (int k0 = 0; k0 < 512; k0 += 16) {
        if (side == 0) {
            int kk = tid & 15, mb = tid >> 4;
#pragma unroll
            for (int it = 0; it < 8; it++) {
                int mm = mb + it * 16;
                As[kk][mm] = A[(m0 + mm) * 512 + (k0 + kk)];
            }
        } else {
            int mm = tid & 127, kb = tid >> 7;
#pragma unroll
            for (int it = 0; it < 8; it++) {
                int kk = kb + it * 2;
                As[kk][mm] = A[(k0 + kk) * 512 + (m0 + mm)];
            }
        }
        {
            int nn = tid & 127, kb = tid >> 7;
#pragma unroll
            for (int it = 0; it < 8; it++) {
                int kk = kb + it * 2;
                Bs[kk][nn] = Wg[(k0 + kk) * 512 + (n0 + nn)];
            }
        }
        __syncthreads();
#pragma unroll
        for (int k = 0; k < 16; k++) {
            float4 a0 = *(const float4*)&As[k][mt];
            float4 a1 = *(const float4*)&As[k][mt + 4];
            ulonglong2 b0 = *(const ulonglong2*)&Bs[k][nt];
            ulonglong2 b1 = *(const ulonglong2*)&Bs[k][nt + 4];
            float a[8] = {a0.x, a0.y, a0.z, a0.w, a1.x, a1.y, a1.z, a1.w};
            unsigned long long bb[4] = {b0.x, b0.y, b1.x, b1.y};
#pragma unroll
            for (int i = 0; i < 8; i++) {
                unsigned long long a2 = pack2(a[i]);
#pragma unroll
                for (int j = 0; j < 4; j++) ffma2(acc[i][j], a2, bb[j]);
            }
        }
        __syncthreads();
    }
#pragma unroll
    for (int i = 0; i < 8; i++) {
        size_t row = (size_t)(m0 + mt + i) * 512 + n0 + nt;
#pragma unroll
        for (int j = 0; j < 4; j++)
            *(unsigned long long*)&Cg[row + 2 * j] = acc[i][j];
    }
}

// ---------------- K2: flat-softmax column sums of the rel blocks ----------------
__global__ void k_relsum() {
    int d = blockIdx.x, b = blockIdx.y, side = blockIdx.z;
    const float* base = (side ? g_TI : g_TJ) + (size_t)b * 512 * 512 + d * 64;
    __shared__ float red[512];
    int tid = threadIdx.x;

    float lmax = -1e30f;
    for (int i = tid; i < 512 * 64; i += 512) {
        int h = i >> 6, p = i & 63;
        lmax = fmaxf(lmax, base[h * 512 + p]);
    }
    red[tid] = lmax; __syncthreads();
    for (int s = 256; s > 0; s >>= 1) {
        if (tid < s) red[tid] = fmaxf(red[tid], red[tid + s]);
        __syncthreads();
    }
    float M = red[0];
    __syncthreads();

    int p = tid & 63, g = tid >> 6;
    float part = 0.f;
    for (int h = g; h < 512; h += 8) part += expf(base[h * 512 + p] - M);
    red[tid] = part; __syncthreads();
    if (tid < 64) {
        float c = 0.f;
#pragma unroll
        for (int gg = 0; gg < 8; gg++) c += red[gg * 64 + tid];
        red[tid] = c;
    }
    __syncthreads();
    if (tid < 32) {
        float t2 = red[tid] + red[tid + 32];
        for (int o = 16; o > 0; o >>= 1) t2 += __shfl_down_sync(0xffffffff, t2, o);
        if (tid == 0) red[256] = t2;
    }
    __syncthreads();
    float total = red[256];
    if (tid < 64)
        g_orel[(((size_t)side * B_ + b) * DEPTH_ + d) * 64 + tid] = red[tid] / total;
}

// ---------------- K3: PT[side][b][d] = T_proj^T[64,512] @ p_x?[512,64] ----------------
__global__ __launch_bounds__(128) void k_pt(const float* __restrict__ pxj,
                                            const float* __restrict__ pxi) {
    int d = blockIdx.x, b = blockIdx.y, side = blockIdx.z;
    const float* A = (side ? g_TI : g_TJ) + (size_t)b * 512 * 512 + 256 + d * 64; // A[k][m], lda=512
    const float* Bw = (side ? pxi : pxj) + (size_t)d * 512 * 64;
    float* C = g_PT + (((size_t)side * B_ + b) * DEPTH_ + d) * 4096;

    __shared__ __align__(16) float As[16][68];
    __shared__ __align__(16) float Bs[16][68];

    int tid = threadIdx.x;
    int trow = tid >> 4, tcol = tid & 15;   // 8 x 16
    int mt = trow * 8, nt = tcol * 4;

    unsigned long long acc[8][2];
#pragma unroll
    for (int i = 0; i < 8; i++) { acc[i][0] = 0ull; acc[i][1] = 0ull; }

    for (int k0 = 0; k0 < 512; k0 += 16) {
        int mm = tid & 63, kb = tid >> 6;   // kb 0..1
#pragma unroll
        for (int it = 0; it < 8; it++) {
            int kk = kb + it * 2;
            As[kk][mm] = A[(k0 + kk) * 512 + mm];
            Bs[kk][mm] = Bw[(k0 + kk) * 64 + mm];
        }
        __syncthreads();
#pragma unroll
        for (int k = 0; k < 16; k++) {
            float4 a0 = *(const float4*)&As[k][mt];
            float4 a1 = *(const float4*)&As[k][mt + 4];
            ulonglong2 bq = *(const ulonglong2*)&Bs[k][nt];
            float a[8] = {a0.x, a0.y, a0.z, a0.w, a1.x, a1.y, a1.z, a1.w};
#pragma unroll
            for (int i = 0; i < 8; i++) {
                unsigned long long a2 = pack2(a[i]);
                ffma2(acc[i][0], a2, bq.x);
                ffma2(acc[i][1], a2, bq.y);
            }
        }
        __syncthreads();
    }
#pragma unroll
    for (int i = 0; i < 8; i++) {
        *(unsigned long long*)&C[(mt + i) * 64 + nt + 0] = acc[i][0];
        *(unsigned long long*)&C[(mt + i) * 64 + nt + 2] = acc[i][1];
    }
}

// ---------------- K4: per-batch epilogue: p_rel softmax, f, x_buf, renorm, depth-sum ----
__global__ void k_final(const float* __restrict__ prel_xj, const float* __restrict__ prel_xi,
                        float* __restrict__ out) {
    int b = blockIdx.x;
    int tid = threadIdx.x;   // 256
    __shared__ float sR[4096];
    __shared__ float red[256];
    __shared__ float prs[2][64];
    __shared__ float fj[64], fi[64];
    __shared__ float sc[2];

    float xm = g_stats[b * 2 + 0];
    float xs = g_stats[b * 2 + 1];
    float acc[16];
#pragma unroll
    for (int r = 0; r < 16; r++) acc[r] = 0.f;

    for (int d = 0; d < DEPTH_; d++) {
        for (int side = 0; side < 2; side++) {
            const float* PT = g_PT + (((size_t)side * B_ + b) * DEPTH_ + d) * 4096;
            const float* WR = (side ? prel_xi : prel_xj) + (size_t)d * 4096;
            // R = PT @ WR  (64x64)
#pragma unroll
            for (int r = 0; r < 16; r++) {
                int e = tid + 256 * r;
                int i = e >> 6, q = e & 63;
                float s = 0.f;
                for (int k = 0; k < 64; k++) s += PT[i * 64 + k] * WR[k * 64 + q];
                sR[e] = s;
            }
            __syncthreads();
            // flat max
            float lm = -1e30f;
#pragma unroll
            for (int r = 0; r < 16; r++) lm = fmaxf(lm, sR[tid + 256 * r]);
            red[tid] = lm; __syncthreads();
            for (int s2 = 128; s2 > 0; s2 >>= 1) {
                if (tid < s2) red[tid] = fmaxf(red[tid], red[tid + s2]);
                __syncthreads();
            }
            float M = red[0];
            __syncthreads();
            // exp column sums
            int q = tid & 63, g = tid >> 6;   // g 0..3, 16 rows each
            float part = 0.f;
            for (int i = g * 16; i < g * 16 + 16; i++) part += expf(sR[i * 64 + q] - M);
            red[tid] = part; __syncthreads();
            if (tid < 64)
                prs[side][tid] = red[tid] + red[tid + 64] + red[tid + 128] + red[tid + 192];
            __syncthreads();
            if (tid < 32) {
                float t2 = prs[side][tid] + prs[side][tid + 32];
                for (int o = 16; o > 0; o >>= 1) t2 += __shfl_down_sync(0xffffffff, t2, o);
                if (tid == 0) sc[side] = t2;
            }
            __syncthreads();
            if (tid < 64) prs[side][tid] /= sc[side];
            __syncthreads();
        }
        if (tid < 64) {
            float oj = g_orel[(((size_t)0 * B_ + b) * DEPTH_ + d) * 64 + tid];
            float oi = g_orel[(((size_t)1 * B_ + b) * DEPTH_ + d) * 64 + tid];
            fj[tid] = sqrtf(oj / prs[0][tid]);
            fi[tid] = sqrtf(oi / prs[1][tid]);
        }
        __syncthreads();

        const float* PTj = g_PT + (((size_t)0 * B_ + b) * DEPTH_ + d) * 4096;
        const float* PTi = g_PT + (((size_t)1 * B_ + b) * DEPTH_ + d) * 4096;
        float v[16], lsum = 0.f, lss = 0.f;
#pragma unroll
        for (int r = 0; r < 16; r++) {
            int e = tid + 256 * r;
            int i = e >> 6, q = e & 63;
            float vv = PTj[i * 64 + q] * fj[i] + PTi[q * 64 + i] * fi[q];
            v[r] = vv; lsum += vv; lss += vv * vv;
        }
        red[tid] = lsum; __syncthreads();
        for (int s2 = 128; s2 > 0; s2 >>= 1) {
            if (tid < s2) red[tid] += red[tid + s2];
            __syncthreads();
        }
        float mean = red[0] / 4096.f;
        __syncthreads();
        red[tid] = lss; __syncthreads();
        for (int s2 = 128; s2 > 0; s2 >>= 1) {
            if (tid < s2) red[tid] += red[tid + s2];
            __syncthreads();
        }
        float var = (red[0] - 4096.f * mean * mean) / 4095.f;
        __syncthreads();
        float inv = xs / (sqrtf(var) + EPS_);
#pragma unroll
        for (int r = 0; r < 16; r++) acc[r] += (v[r] - mean) * inv + xm;
    }
#pragma unroll
    for (int r = 0; r < 16; r++) out[(size_t)b * 4096 + tid + 256 * r] = acc[r];
}

// ---------------- launch ----------------
extern "C" void kernel_launch(void* const* d_in, const int* in_sizes, int n_in,
                              void* d_out, int out_size) {
    const float* x        = (const float*)d_in[0];
    const float* o_xj     = (const float*)d_in[1];
    const float* o_xi     = (const float*)d_in[2];
    const float* p_xj     = (const float*)d_in[3];
    const float* p_xi     = (const float*)d_in[4];
    const float* o_rel_xj = (const float*)d_in[5];
    const float* o_rel_xi = (const float*)d_in[6];
    const float* p_rel_xj = (const float*)d_in[7];
    const float* p_rel_xi = (const float*)d_in[8];
    float* out = (float*)d_out;

    k_prep<<<1024, 512>>>(o_xj, o_xi, o_rel_xj, o_rel_xi);
    k_stats<<<B_, 256>>>(x);
    k_bigmm<<<dim3(4, 4, B_ * 2), 256>>>(x);
    k_relsum<<<dim3(DEPTH_, B_, 2), 512>>>();
    k_pt<<<dim3(DEPTH_, B_, 2), 128>>>(p_xj, p_xi);
    k_final<<<B_, 256>>>(p_rel_xj, p_rel_xi, out);
}

// round 7
// speedup vs baseline: 2.9967x; 2.9967x over previous
#include <cuda_runtime.h>
#include <cuda_bf16.h>
#include <math.h>

#define B_    128
#define H_    512
#define W_    512
#define P_    64
#define DEPTH_ 4
#define EPS_  1e-5f

// ---------------- scratch (__device__ globals; no runtime allocation) ----------------
// TJ[b][h][n]: n in [0,256) = x @ o_rel_xj (d*64+p), n in [256,512) = x @ o_xj
// TI[b][w][n]: same with xt @ o_rel_xi / o_xi
__device__ __align__(16) float g_TJ[(size_t)B_ * 512 * 512];
__device__ __align__(16) float g_TI[(size_t)B_ * 512 * 512];
__device__ __align__(16) __nv_bfloat16 g_xh[(size_t)B_ * 512 * 512];   // x hi
__device__ __align__(16) __nv_bfloat16 g_xl[(size_t)B_ * 512 * 512];   // x lo
__device__ __align__(16) __nv_bfloat16 g_xth[(size_t)B_ * 512 * 512];  // x^T hi
__device__ __align__(16) __nv_bfloat16 g_xtl[(size_t)B_ * 512 * 512];  // x^T lo
__device__ __align__(16) __nv_bfloat16 g_WTh[2][512 * 512];            // W^T hi [side][n][k]
__device__ __align__(16) __nv_bfloat16 g_WTl[2][512 * 512];            // W^T lo
__device__ float g_PT[(size_t)2 * B_ * DEPTH_ * 64 * 64];  // [side][b][d][p][q]
__device__ float g_orel[(size_t)2 * B_ * DEPTH_ * 64];     // [side][b][d][p]
__device__ float g_stats[B_ * 2];                          // mean*scale, std*scale

// ---------------- small helpers ----------------
__device__ __forceinline__ unsigned long long pack2(float x) {
    unsigned long long r;
    asm("mov.b64 %0, {%1, %1};" : "=l"(r) : "f"(x));
    return r;
}
__device__ __forceinline__ void ffma2(unsigned long long &acc, unsigned long long a,
                                      unsigned long long b) {
    asm("fma.rn.f32x2 %0, %1, %2, %0;" : "+l"(acc) : "l"(a), "l"(b));
}
__device__ __forceinline__ unsigned smem_u32(const void* p) {
    unsigned a;
    asm("{ .reg .u64 t; cvta.to.shared.u64 t, %1; cvt.u32.u64 %0, t; }" : "=r"(a) : "l"(p));
    return a;
}
__device__ __forceinline__ void cpa16(unsigned saddr, const void* g) {
    asm volatile("cp.async.cg.shared.global [%0], [%1], 16;"
                 :: "r"(saddr), "l"(g) : "memory");
}
__device__ __forceinline__ void ldsm4(unsigned* r, unsigned addr) {
    asm volatile("ldmatrix.sync.aligned.m8n8.x4.shared.b16 {%0,%1,%2,%3}, [%4];"
                 : "=r"(r[0]), "=r"(r[1]), "=r"(r[2]), "=r"(r[3]) : "r"(addr));
}
__device__ __forceinline__ void mma16816(float* d, const unsigned* a, const unsigned* b) {
    asm volatile(
        "mma.sync.aligned.m16n8k16.row.col.f32.bf16.bf16.f32 "
        "{%0,%1,%2,%3}, {%4,%5,%6,%7}, {%8,%9}, {%0,%1,%2,%3};"
        : "+f"(d[0]), "+f"(d[1]), "+f"(d[2]), "+f"(d[3])
        : "r"(a[0]), "r"(a[1]), "r"(a[2]), "r"(a[3]), "r"(b[0]), "r"(b[1]));
}

// ---------------- K0a: assemble combined transposed bf16 hi/lo weights ----------------
__global__ void k_prep(const float* __restrict__ o_xj, const float* __restrict__ o_xi,
                       const float* __restrict__ orel_xj, const float* __restrict__ orel_xi) {
    int idx = blockIdx.x * blockDim.x + threadIdx.x;   // 0 .. 2*262144-1
    int which = idx >> 18;
    int e = idx & 262143;
    int n = e >> 9, k = e & 511;
    int rel = (n < 256);
    int d = (n & 255) >> 6;
    int p = n & 63;
    const float* src = (which == 0) ? (rel ? orel_xj : o_xj) : (rel ? orel_xi : o_xi);
    float v = src[(d * 512 + k) * 64 + p];
    __nv_bfloat16 h = __float2bfloat16(v);
    g_WTh[which][n * 512 + k] = h;
    g_WTl[which][n * 512 + k] = __float2bfloat16(v - __bfloat162float(h));
}

// ---------------- K0b: convert x -> bf16 hi/lo, plus transposed copies ----------------
__global__ void k_conv(const float* __restrict__ x) {
    int b = blockIdx.z;
    int h0 = blockIdx.y * 32, w0 = blockIdx.x * 32;
    __shared__ float t[32][33];
    int tx = threadIdx.x, ty = threadIdx.y;  // 32 x 8
    const float* xb = x + (size_t)b * 262144;
    size_t ob = (size_t)b * 262144;
#pragma unroll
    for (int i = 0; i < 4; i++) {
        int r = ty + i * 8;
        float v = xb[(size_t)(h0 + r) * 512 + w0 + tx];
        t[r][tx] = v;
        __nv_bfloat16 hh = __float2bfloat16(v);
        size_t o = ob + (size_t)(h0 + r) * 512 + w0 + tx;
        g_xh[o] = hh;
        g_xl[o] = __float2bfloat16(v - __bfloat162float(hh));
    }
    __syncthreads();
#pragma unroll
    for (int i = 0; i < 4; i++) {
        int r = ty + i * 8;
        float v = t[tx][r];  // x[h0+tx][w0+r]
        __nv_bfloat16 hh = __float2bfloat16(v);
        size_t o = ob + (size_t)(w0 + r) * 512 + h0 + tx;
        g_xth[o] = hh;
        g_xtl[o] = __float2bfloat16(v - __bfloat162float(hh));
    }
}

// ---------------- K0c: per-batch mean/std of x (scaled) ----------------
__global__ void k_stats(const float* __restrict__ x) {
    int b = blockIdx.x, tid = threadIdx.x;
    const float* xb = x + (size_t)b * H_ * W_;
    float s = 0.f, ss = 0.f;
    for (int i = tid; i < H_ * W_; i += 256) {
        float v = xb[i];
        s += v; ss += v * v;
    }
    __shared__ float r1[256], r2[256];
    r1[tid] = s; r2[tid] = ss; __syncthreads();
    for (int st = 128; st > 0; st >>= 1) {
        if (tid < st) { r1[tid] += r1[tid + st]; r2[tid] += r2[tid + st]; }
        __syncthreads();
    }
    if (tid == 0) {
        float n = (float)(H_ * W_);
        float mean = r1[0] / n;
        float var = (r2[0] - n * mean * mean) / (n - 1.f);
        float scale = ((float)H_ / P_) * ((float)W_ / P_);   // 64
        g_stats[b * 2 + 0] = mean * scale;
        g_stats[b * 2 + 1] = sqrtf(var) * scale;
    }
}

// ---------------- K1: warp-MMA bf16-split GEMM, CTA tile 128x128, Kc=64 ----------------
// C[m][n] = sum_k A[m][k]*W[k][n];  mma computes A[m][k] * B[n][k] with B = W^T.
// 3 products Ah*Bh + Ah*Bl + Al*Bh accumulate in fp32.
#define STAGE_BYTES 65536
#define OFF_AH 0
#define OFF_AL 16384
#define OFF_BH 32768
#define OFF_BL 49152
#define SMEM_GEMM (2 * STAGE_BYTES)

__device__ __forceinline__ unsigned swz(int row, int colb) {
    return (unsigned)(row * 128 + (colb ^ ((row & 7) << 4)));
}

__device__ __forceinline__ void cp_stage(unsigned sbase, int buf,
    const __nv_bfloat16* Ah, const __nv_bfloat16* Al,
    const __nv_bfloat16* Bh, const __nv_bfloat16* Bl,
    int k0, int tid)
{
    unsigned base = sbase + buf * STAGE_BYTES;
#pragma unroll
    for (int i = 0; i < 4; i++) {
        int q = tid + 256 * i;
        int row = q >> 3, c = q & 7;
        unsigned o = swz(row, c * 16);
        const char* pa = (const char*)(Ah + (size_t)row * 512 + k0) + c * 16;
        const char* pl = (const char*)(Al + (size_t)row * 512 + k0) + c * 16;
        const char* pb = (const char*)(Bh + (size_t)row * 512 + k0) + c * 16;
        const char* pc = (const char*)(Bl + (size_t)row * 512 + k0) + c * 16;
        cpa16(base + OFF_AH + o, pa);
        cpa16(base + OFF_AL + o, pl);
        cpa16(base + OFF_BH + o, pb);
        cpa16(base + OFF_BL + o, pc);
    }
    asm volatile("cp.async.commit_group;" ::: "memory");
}

__global__ __launch_bounds__(256, 1) void k_bigmm_wm() {
    extern __shared__ char smem[];
    unsigned sbase = smem_u32(smem);
    int tid = threadIdx.x, lane = tid & 31, wid = tid >> 5;
    int n0 = blockIdx.x * 128, m0 = blockIdx.y * 128;
    int side = blockIdx.z & 1, b = blockIdx.z >> 1;

    const __nv_bfloat16* Ah = (side ? g_xth : g_xh) + (size_t)b * 262144 + (size_t)m0 * 512;
    const __nv_bfloat16* Al = (side ? g_xtl : g_xl) + (size_t)b * 262144 + (size_t)m0 * 512;
    const __nv_bfloat16* Bh = g_WTh[side] + (size_t)n0 * 512;
    const __nv_bfloat16* Bl = g_WTl[side] + (size_t)n0 * 512;
    float* Cg = (side ? g_TI : g_TJ) + (size_t)b * 262144;

    const int mw = (wid & 3) * 32;    // warp m offset within tile
    const int nw = (wid >> 2) * 64;   // warp n offset within tile

    float acc[2][8][4];
#pragma unroll
    for (int i = 0; i < 2; i++)
#pragma unroll
        for (int j = 0; j < 8; j++)
#pragma unroll
            for (int k = 0; k < 4; k++) acc[i][j][k] = 0.f;

    cp_stage(sbase, 0, Ah, Al, Bh, Bl, 0, tid);

    for (int c = 0; c < 8; c++) {
        asm volatile("cp.async.wait_group 0;" ::: "memory");
        __syncthreads();
        if (c < 7) cp_stage(sbase, (c + 1) & 1, Ah, Al, Bh, Bl, (c + 1) * 64, tid);
        unsigned tb = sbase + (c & 1) * STAGE_BYTES;

#pragma unroll
        for (int kk = 0; kk < 4; kk++) {
            int ko2 = kk * 32;   // byte offset of this k16 block within 128B row
            unsigned ah[2][4], al[2][4];
#pragma unroll
            for (int mb = 0; mb < 2; mb++) {
                int row = mw + mb * 16 + (lane & 7) + ((lane >> 3) & 1) * 8;
                int colb = ko2 + ((lane >> 4) & 1) * 16;
                unsigned ad = tb + OFF_AH + swz(row, colb);
                ldsm4(ah[mb], ad);
                ldsm4(al[mb], ad + (OFF_AL - OFF_AH));
            }
            unsigned bh[8][2], bl[8][2];
#pragma unroll
            for (int nb2 = 0; nb2 < 4; nb2++) {
                int mat = lane >> 3;
                int row = nw + nb2 * 16 + (lane & 7) + (mat >> 1) * 8;
                int colb = ko2 + (mat & 1) * 16;
                unsigned bd = tb + OFF_BH + swz(row, colb);
                unsigned t[4];
                ldsm4(t, bd);
                bh[nb2 * 2][0] = t[0]; bh[nb2 * 2][1] = t[1];
                bh[nb2 * 2 + 1][0] = t[2]; bh[nb2 * 2 + 1][1] = t[3];
                ldsm4(t, bd + (OFF_BL - OFF_BH));
                bl[nb2 * 2][0] = t[0]; bl[nb2 * 2][1] = t[1];
                bl[nb2 * 2 + 1][0] = t[2]; bl[nb2 * 2 + 1][1] = t[3];
            }
#pragma unroll
            for (int mb = 0; mb < 2; mb++)
#pragma unroll
                for (int nb = 0; nb < 8; nb++) {
                    mma16816(acc[mb][nb], ah[mb], bh[nb]);
                    mma16816(acc[mb][nb], ah[mb], bl[nb]);
                    mma16816(acc[mb][nb], al[mb], bh[nb]);
                }
        }
        __syncthreads();
    }

    // epilogue: direct fp32 stores (float2 per frag half)
#pragma unroll
    for (int mb = 0; mb < 2; mb++) {
        int r = m0 + mw + mb * 16 + (lane >> 2);
#pragma unroll
        for (int nb = 0; nb < 8; nb++) {
            int cc = n0 + nw + nb * 8 + (lane & 3) * 2;
            float2 v0 = make_float2(acc[mb][nb][0], acc[mb][nb][1]);
            float2 v1 = make_float2(acc[mb][nb][2], acc[mb][nb][3]);
            *(float2*)&Cg[(size_t)r * 512 + cc] = v0;
            *(float2*)&Cg[(size_t)(r + 8) * 512 + cc] = v1;
        }
    }
}

// ---------------- K2: flat-softmax column sums of the rel blocks ----------------
__global__ void k_relsum() {
    int d = blockIdx.x, b = blockIdx.y, side = blockIdx.z;
    const float* base = (side ? g_TI : g_TJ) + (size_t)b * 512 * 512 + d * 64;
    __shared__ float red[512];
    int tid = threadIdx.x;

    float lmax = -1e30f;
    for (int i = tid; i < 512 * 64; i += 512) {
        int h = i >> 6, p = i & 63;
        lmax = fmaxf(lmax, base[h * 512 + p]);
    }
    red[tid] = lmax; __syncthreads();
    for (int s = 256; s > 0; s >>= 1) {
        if (tid < s) red[tid] = fmaxf(red[tid], red[tid + s]);
        __syncthreads();
    }
    float M = red[0];
    __syncthreads();

    int p = tid & 63, g = tid >> 6;
    float part = 0.f;
    for (int h = g; h < 512; h += 8) part += expf(base[h * 512 + p] - M);
    red[tid] = part; __syncthreads();
    if (tid < 64) {
        float c = 0.f;
#pragma unroll
        for (int gg = 0; gg < 8; gg++) c += red[gg * 64 + tid];
        red[tid] = c;
    }
    __syncthreads();
    if (tid < 32) {
        float t2 = red[tid] + red[tid + 32];
        for (int o = 16; o > 0; o >>= 1) t2 += __shfl_down_sync(0xffffffff, t2, o);
        if (tid == 0) red[256] = t2;
    }
    __syncthreads();
    float total = red[256];
    if (tid < 64)
        g_orel[(((size_t)side * B_ + b) * DEPTH_ + d) * 64 + tid] = red[tid] / total;
}

// ---------------- K3: PT[side][b][d] = T_proj^T[64,512] @ p_x?[512,64] ----------------
__global__ __launch_bounds__(128) void k_pt(const float* __restrict__ pxj,
                                            const float* __restrict__ pxi) {
    int d = blockIdx.x, b = blockIdx.y, side = blockIdx.z;
    const float* A = (side ? g_TI : g_TJ) + (size_t)b * 512 * 512 + 256 + d * 64; // A[k][m], lda=512
    const float* Bw = (side ? pxi : pxj) + (size_t)d * 512 * 64;
    float* C = g_PT + (((size_t)side * B_ + b) * DEPTH_ + d) * 4096;

    __shared__ __align__(16) float As[16][68];
    __shared__ __align__(16) float Bs[16][68];

    int tid = threadIdx.x;
    int trow = tid >> 4, tcol = tid & 15;   // 8 x 16
    int mt = trow * 8, nt = tcol * 4;

    unsigned long long acc[8][2];
#pragma unroll
    for (int i = 0; i < 8; i++) { acc[i][0] = 0ull; acc[i][1] = 0ull; }

    for (int k0 = 0; k0 < 512; k0 += 16) {
        int mm = tid & 63, kb = tid >> 6;   // kb 0..1
#pragma unroll
        for (int it = 0; it < 8; it++) {
            int kk = kb + it * 2;
            As[kk][mm] = A[(k0 + kk) * 512 + mm];
            Bs[kk][mm] = Bw[(k0 + kk) * 64 + mm];
        }
        __syncthreads();
#pragma unroll
        for (int k = 0; k < 16; k++) {
            float4 a0 = *(const float4*)&As[k][mt];
            float4 a1 = *(const float4*)&As[k][mt + 4];
            ulonglong2 bq = *(const ulonglong2*)&Bs[k][nt];
            float a[8] = {a0.x, a0.y, a0.z, a0.w, a1.x, a1.y, a1.z, a1.w};
#pragma unroll
            for (int i = 0; i < 8; i++) {
                unsigned long long a2 = pack2(a[i]);
                ffma2(acc[i][0], a2, bq.x);
                ffma2(acc[i][1], a2, bq.y);
            }
        }
        __syncthreads();
    }
#pragma unroll
    for (int i = 0; i < 8; i++) {
        *(unsigned long long*)&C[(mt + i) * 64 + nt + 0] = acc[i][0];
        *(unsigned long long*)&C[(mt + i) * 64 + nt + 2] = acc[i][1];
    }
}

// ---------------- K4: per-batch epilogue: p_rel softmax, f, x_buf, renorm, depth-sum ----
__global__ void k_final(const float* __restrict__ prel_xj, const float* __restrict__ prel_xi,
                        float* __restrict__ out) {
    int b = blockIdx.x;
    int tid = threadIdx.x;   // 256
    __shared__ float sR[4096];
    __shared__ float red[256];
    __shared__ float prs[2][64];
    __shared__ float fj[64], fi[64];
    __shared__ float sc[2];

    float xm = g_stats[b * 2 + 0];
    float xs = g_stats[b * 2 + 1];
    float acc[16];
#pragma unroll
    for (int r = 0; r < 16; r++) acc[r] = 0.f;

    for (int d = 0; d < DEPTH_; d++) {
        for (int side = 0; side < 2; side++) {
            const float* PT = g_PT + (((size_t)side * B_ + b) * DEPTH_ + d) * 4096;
            const float* WR = (side ? prel_xi : prel_xj) + (size_t)d * 4096;
#pragma unroll
            for (int r = 0; r < 16; r++) {
                int e = tid + 256 * r;
                int i = e >> 6, q = e & 63;
                float s = 0.f;
                for (int k = 0; k < 64; k++) s += PT[i * 64 + k] * WR[k * 64 + q];
                sR[e] = s;
            }
            __syncthreads();
            float lm = -1e30f;
#pragma unroll
            for (int r = 0; r < 16; r++) lm = fmaxf(lm, sR[tid + 256 * r]);
            red[tid] = lm; __syncthreads();
            for (int s2 = 128; s2 > 0; s2 >>= 1) {
                if (tid < s2) red[tid] = fmaxf(red[tid], red[tid + s2]);
                __syncthreads();
            }
            float M = red[0];
            __syncthreads();
            int q = tid & 63, g = tid >> 6;
            float part = 0.f;
            for (int i = g * 16; i < g * 16 + 16; i++) part += expf(sR[i * 64 + q] - M);
            red[tid] = part; __syncthreads();
            if (tid < 64)
                prs[side][tid] = red[tid] + red[tid + 64] + red[tid + 128] + red[tid + 192];
            __syncthreads();
            if (tid < 32) {
                float t2 = prs[side][tid] + prs[side][tid + 32];
                for (int o = 16; o > 0; o >>= 1) t2 += __shfl_down_sync(0xffffffff, t2, o);
                if (tid == 0) sc[side] = t2;
            }
            __syncthreads();
            if (tid < 64) prs[side][tid] /= sc[side];
            __syncthreads();
        }
        if (tid < 64) {
            float oj = g_orel[(((size_t)0 * B_ + b) * DEPTH_ + d) * 64 + tid];
            float oi = g_orel[(((size_t)1 * B_ + b) * DEPTH_ + d) * 64 + tid];
            fj[tid] = sqrtf(oj / prs[0][tid]);
            fi[tid] = sqrtf(oi / prs[1][tid]);
        }
        __syncthreads();

        const float* PTj = g_PT + (((size_t)0 * B_ + b) * DEPTH_ + d) * 4096;
        const float* PTi = g_PT + (((size_t)1 * B_ + b) * DEPTH_ + d) * 4096;
        float v[16], lsum = 0.f, lss = 0.f;
#pragma unroll
        for (int r = 0; r < 16; r++) {
            int e = tid + 256 * r;
            int i = e >> 6, q = e & 63;
            float vv = PTj[i * 64 + q] * fj[i] + PTi[q * 64 + i] * fi[q];
            v[r] = vv; lsum += vv; lss += vv * vv;
        }
        red[tid] = lsum; __syncthreads();
        for (int s2 = 128; s2 > 0; s2 >>= 1) {
            if (tid < s2) red[tid] += red[tid + s2];
            __syncthreads();
        }
        float mean = red[0] / 4096.f;
        __syncthreads();
        red[tid] = lss; __syncthreads();
        for (int s2 = 128; s2 > 0; s2 >>= 1) {
            if (tid < s2) red[tid] += red[tid + s2];
            __syncthreads();
        }
        float var = (red[0] - 4096.f * mean * mean) / 4095.f;
        __syncthreads();
        float inv = xs / (sqrtf(var) + EPS_);
#pragma unroll
        for (int r = 0; r < 16; r++) acc[r] += (v[r] - mean) * inv + xm;
    }
#pragma unroll
    for (int r = 0; r < 16; r++) out[(size_t)b * 4096 + tid + 256 * r] = acc[r];
}

// ---------------- launch ----------------
extern "C" void kernel_launch(void* const* d_in, const int* in_sizes, int n_in,
                              void* d_out, int out_size) {
    const float* x        = (const float*)d_in[0];
    const float* o_xj     = (const float*)d_in[1];
    const float* o_xi     = (const float*)d_in[2];
    const float* p_xj     = (const float*)d_in[3];
    const float* p_xi     = (const float*)d_in[4];
    const float* o_rel_xj = (const float*)d_in[5];
    const float* o_rel_xi = (const float*)d_in[6];
    const float* p_rel_xj = (const float*)d_in[7];
    const float* p_rel_xi = (const float*)d_in[8];
    float* out = (float*)d_out;

    // not a stream op; safe under graph capture, deterministic every call
    cudaFuncSetAttribute(k_bigmm_wm, cudaFuncAttributeMaxDynamicSharedMemorySize, SMEM_GEMM);

    k_prep<<<1024, 512>>>(o_xj, o_xi, o_rel_xj, o_rel_xi);
    k_conv<<<dim3(16, 16, B_), dim3(32, 8)>>>(x);
    k_stats<<<B_, 256>>>(x);
    k_bigmm_wm<<<dim3(4, 4, B_ * 2), 256, SMEM_GEMM>>>();
    k_relsum<<<dim3(DEPTH_, B_, 2), 512>>>();
    k_pt<<<dim3(DEPTH_, B_, 2), 128>>>(p_xj, p_xi);
    k_final<<<B_, 256>>>(p_rel_xj, p_rel_xi, out);
}

// round 8
// speedup vs baseline: 3.5529x; 1.1856x over previous
#include <cuda_runtime.h>
#include <cuda_bf16.h>
#include <math.h>

#define B_    128
#define H_    512
#define W_    512
#define P_    64
#define DEPTH_ 4
#define EPS_  1e-5f

// ---------------- scratch (__device__ globals; no runtime allocation) ----------------
// TJ[b][h][n]: n in [0,256) = x @ o_rel_xj (d*64+p), n in [256,512) = x @ o_xj
// TI[b][w][n]: same with xt @ o_rel_xi / o_xi
__device__ __align__(16) float g_TJ[(size_t)B_ * 512 * 512];
__device__ __align__(16) float g_TI[(size_t)B_ * 512 * 512];
__device__ __align__(16) __nv_bfloat16 g_xh[(size_t)B_ * 512 * 512];   // x hi
__device__ __align__(16) __nv_bfloat16 g_xl[(size_t)B_ * 512 * 512];   // x lo
__device__ __align__(16) __nv_bfloat16 g_xth[(size_t)B_ * 512 * 512];  // x^T hi
__device__ __align__(16) __nv_bfloat16 g_xtl[(size_t)B_ * 512 * 512];  // x^T lo
__device__ __align__(16) __nv_bfloat16 g_WTh[2][512 * 512];            // W^T hi [side][n][k]
__device__ __align__(16) __nv_bfloat16 g_WTl[2][512 * 512];            // W^T lo
__device__ float g_PT[(size_t)2 * B_ * DEPTH_ * 64 * 64];  // [side][b][d][p][q]
__device__ float g_orel[(size_t)2 * B_ * DEPTH_ * 64];     // [side][b][d][p] normalized
__device__ float g_prs[(size_t)2 * B_ * DEPTH_ * 64];      // p_rel colsums, normalized
__device__ float g_stats[B_ * 2];                          // mean*scale, std*scale

// ---------------- small helpers ----------------
__device__ __forceinline__ unsigned long long pack2(float x) {
    unsigned long long r;
    asm("mov.b64 %0, {%1, %1};" : "=l"(r) : "f"(x));
    return r;
}
__device__ __forceinline__ void ffma2(unsigned long long &acc, unsigned long long a,
                                      unsigned long long b) {
    asm("fma.rn.f32x2 %0, %1, %2, %0;" : "+l"(acc) : "l"(a), "l"(b));
}
__device__ __forceinline__ unsigned smem_u32(const void* p) {
    unsigned a;
    asm("{ .reg .u64 t; cvta.to.shared.u64 t, %1; cvt.u32.u64 %0, t; }" : "=r"(a) : "l"(p));
    return a;
}
__device__ __forceinline__ void cpa16(unsigned saddr, const void* g) {
    asm volatile("cp.async.cg.shared.global [%0], [%1], 16;"
                 :: "r"(saddr), "l"(g) : "memory");
}
__device__ __forceinline__ void ldsm4(unsigned* r, unsigned addr) {
    asm volatile("ldmatrix.sync.aligned.m8n8.x4.shared.b16 {%0,%1,%2,%3}, [%4];"
                 : "=r"(r[0]), "=r"(r[1]), "=r"(r[2]), "=r"(r[3]) : "r"(addr));
}
__device__ __forceinline__ void mma16816(float* d, const unsigned* a, const unsigned* b) {
    asm volatile(
        "mma.sync.aligned.m16n8k16.row.col.f32.bf16.bf16.f32 "
        "{%0,%1,%2,%3}, {%4,%5,%6,%7}, {%8,%9}, {%0,%1,%2,%3};"
        : "+f"(d[0]), "+f"(d[1]), "+f"(d[2]), "+f"(d[3])
        : "r"(a[0]), "r"(a[1]), "r"(a[2]), "r"(a[3]), "r"(b[0]), "r"(b[1]));
}

// ---------------- K0a: assemble combined transposed bf16 hi/lo weights ----------------
__global__ void k_prep(const float* __restrict__ o_xj, const float* __restrict__ o_xi,
                       const float* __restrict__ orel_xj, const float* __restrict__ orel_xi) {
    int idx = blockIdx.x * blockDim.x + threadIdx.x;   // 0 .. 2*262144-1
    int which = idx >> 18;
    int e = idx & 262143;
    int n = e >> 9, k = e & 511;
    int rel = (n < 256);
    int d = (n & 255) >> 6;
    int p = n & 63;
    const float* src = (which == 0) ? (rel ? orel_xj : o_xj) : (rel ? orel_xi : o_xi);
    float v = src[(d * 512 + k) * 64 + p];
    __nv_bfloat16 h = __float2bfloat16(v);
    g_WTh[which][n * 512 + k] = h;
    g_WTl[which][n * 512 + k] = __float2bfloat16(v - __bfloat162float(h));
}

// ---------------- K0b: convert x -> bf16 hi/lo, plus transposed copies ----------------
__global__ void k_conv(const float* __restrict__ x) {
    int b = blockIdx.z;
    int h0 = blockIdx.y * 32, w0 = blockIdx.x * 32;
    __shared__ float t[32][33];
    int tx = threadIdx.x, ty = threadIdx.y;  // 32 x 8
    const float* xb = x + (size_t)b * 262144;
    size_t ob = (size_t)b * 262144;
#pragma unroll
    for (int i = 0; i < 4; i++) {
        int r = ty + i * 8;
        float v = xb[(size_t)(h0 + r) * 512 + w0 + tx];
        t[r][tx] = v;
        __nv_bfloat16 hh = __float2bfloat16(v);
        size_t o = ob + (size_t)(h0 + r) * 512 + w0 + tx;
        g_xh[o] = hh;
        g_xl[o] = __float2bfloat16(v - __bfloat162float(hh));
    }
    __syncthreads();
#pragma unroll
    for (int i = 0; i < 4; i++) {
        int r = ty + i * 8;
        float v = t[tx][r];  // x[h0+tx][w0+r]
        __nv_bfloat16 hh = __float2bfloat16(v);
        size_t o = ob + (size_t)(w0 + r) * 512 + h0 + tx;
        g_xth[o] = hh;
        g_xtl[o] = __float2bfloat16(v - __bfloat162float(hh));
    }
}

// ---------------- K0c: per-batch mean/std of x (scaled) ----------------
__global__ void k_stats(const float* __restrict__ x) {
    int b = blockIdx.x, tid = threadIdx.x;
    const float* xb = x + (size_t)b * H_ * W_;
    float s = 0.f, ss = 0.f;
    for (int i = tid; i < H_ * W_; i += 256) {
        float v = xb[i];
        s += v; ss += v * v;
    }
    __shared__ float r1[256], r2[256];
    r1[tid] = s; r2[tid] = ss; __syncthreads();
    for (int st = 128; st > 0; st >>= 1) {
        if (tid < st) { r1[tid] += r1[tid + st]; r2[tid] += r2[tid + st]; }
        __syncthreads();
    }
    if (tid == 0) {
        float n = (float)(H_ * W_);
        float mean = r1[0] / n;
        float var = (r2[0] - n * mean * mean) / (n - 1.f);
        float scale = ((float)H_ / P_) * ((float)W_ / P_);   // 64
        g_stats[b * 2 + 0] = mean * scale;
        g_stats[b * 2 + 1] = sqrtf(var) * scale;
    }
}

// ---------------- K1: warp-MMA bf16 GEMM, CTA 128x128, Kc=64, 3-stage cp.async ----
// rel n-tiles (n0<256): single product Ah*Bh (softmax-bound accuracy budget)
// proj n-tiles: 3 products Ah*Bh + Ah*Bl + Al*Bh
#define STAGE_BYTES 65536
#define OFF_AH 0
#define OFF_AL 16384
#define OFF_BH 32768
#define OFF_BL 49152
#define NSTAGE 3
#define SMEM_GEMM (NSTAGE * STAGE_BYTES)

__device__ __forceinline__ unsigned swz(int row, int colb) {
    return (unsigned)(row * 128 + (colb ^ ((row & 7) << 4)));
}

__device__ __forceinline__ void cp_stage(unsigned sbase, int buf,
    const __nv_bfloat16* Ah, const __nv_bfloat16* Al,
    const __nv_bfloat16* Bh, const __nv_bfloat16* Bl,
    int k0, int tid, bool full)
{
    unsigned base = sbase + buf * STAGE_BYTES;
#pragma unroll
    for (int i = 0; i < 4; i++) {
        int q = tid + 256 * i;
        int row = q >> 3, c = q & 7;
        unsigned o = swz(row, c * 16);
        cpa16(base + OFF_AH + o, (const char*)(Ah + (size_t)row * 512 + k0) + c * 16);
        cpa16(base + OFF_BH + o, (const char*)(Bh + (size_t)row * 512 + k0) + c * 16);
        if (full) {
            cpa16(base + OFF_AL + o, (const char*)(Al + (size_t)row * 512 + k0) + c * 16);
            cpa16(base + OFF_BL + o, (const char*)(Bl + (size_t)row * 512 + k0) + c * 16);
        }
    }
    asm volatile("cp.async.commit_group;" ::: "memory");
}

__global__ __launch_bounds__(256, 1) void k_bigmm_wm() {
    extern __shared__ char smem[];
    unsigned sbase = smem_u32(smem);
    int tid = threadIdx.x, lane = tid & 31, wid = tid >> 5;
    int n0 = blockIdx.x * 128, m0 = blockIdx.y * 128;
    int side = blockIdx.z & 1, b = blockIdx.z >> 1;
    const bool full = (n0 >= 256);   // proj half needs hi/lo split

    const __nv_bfloat16* Ah = (side ? g_xth : g_xh) + (size_t)b * 262144 + (size_t)m0 * 512;
    const __nv_bfloat16* Al = (side ? g_xtl : g_xl) + (size_t)b * 262144 + (size_t)m0 * 512;
    const __nv_bfloat16* Bh = g_WTh[side] + (size_t)n0 * 512;
    const __nv_bfloat16* Bl = g_WTl[side] + (size_t)n0 * 512;
    float* Cg = (side ? g_TI : g_TJ) + (size_t)b * 262144;

    const int mw = (wid & 3) * 32;    // warp m offset
    const int nw = (wid >> 2) * 64;   // warp n offset

    float acc[2][8][4];
#pragma unroll
    for (int i = 0; i < 2; i++)
#pragma unroll
        for (int j = 0; j < 8; j++)
#pragma unroll
            for (int k = 0; k < 4; k++) acc[i][j][k] = 0.f;

    cp_stage(sbase, 0, Ah, Al, Bh, Bl, 0, tid, full);
    cp_stage(sbase, 1, Ah, Al, Bh, Bl, 64, tid, full);

    for (int c = 0; c < 8; c++) {
        if (c == 7) asm volatile("cp.async.wait_group 0;" ::: "memory");
        else        asm volatile("cp.async.wait_group 1;" ::: "memory");
        __syncthreads();
        if (c + 2 < 8)
            cp_stage(sbase, (c + 2) % NSTAGE, Ah, Al, Bh, Bl, (c + 2) * 64, tid, full);
        unsigned tb = sbase + (c % NSTAGE) * STAGE_BYTES;

#pragma unroll
        for (int kk = 0; kk < 4; kk++) {
            int ko2 = kk * 32;   // byte offset of this k16 block within 128B row
            unsigned ah[2][4], al[2][4];
#pragma unroll
            for (int mb = 0; mb < 2; mb++) {
                int row = mw + mb * 16 + (lane & 7) + ((lane >> 3) & 1) * 8;
                int colb = ko2 + ((lane >> 4) & 1) * 16;
                unsigned ad = tb + OFF_AH + swz(row, colb);
                ldsm4(ah[mb], ad);
                if (full) ldsm4(al[mb], ad + (OFF_AL - OFF_AH));
            }
            unsigned bh[8][2], bl[8][2];
#pragma unroll
            for (int nb2 = 0; nb2 < 4; nb2++) {
                int mat = lane >> 3;
                int row = nw + nb2 * 16 + (lane & 7) + (mat >> 1) * 8;
                int colb = ko2 + (mat & 1) * 16;
                unsigned bd = tb + OFF_BH + swz(row, colb);
                unsigned t[4];
                ldsm4(t, bd);
                bh[nb2 * 2][0] = t[0]; bh[nb2 * 2][1] = t[1];
                bh[nb2 * 2 + 1][0] = t[2]; bh[nb2 * 2 + 1][1] = t[3];
                if (full) {
                    ldsm4(t, bd + (OFF_BL - OFF_BH));
                    bl[nb2 * 2][0] = t[0]; bl[nb2 * 2][1] = t[1];
                    bl[nb2 * 2 + 1][0] = t[2]; bl[nb2 * 2 + 1][1] = t[3];
                }
            }
#pragma unroll
            for (int mb = 0; mb < 2; mb++)
#pragma unroll
                for (int nb = 0; nb < 8; nb++) {
                    mma16816(acc[mb][nb], ah[mb], bh[nb]);
                    if (full) {
                        mma16816(acc[mb][nb], ah[mb], bl[nb]);
                        mma16816(acc[mb][nb], al[mb], bh[nb]);
                    }
                }
        }
        __syncthreads();
    }

    // epilogue: direct fp32 stores
#pragma unroll
    for (int mb = 0; mb < 2; mb++) {
        int r = m0 + mw + mb * 16 + (lane >> 2);
#pragma unroll
        for (int nb = 0; nb < 8; nb++) {
            int cc = n0 + nw + nb * 8 + (lane & 3) * 2;
            float2 v0 = make_float2(acc[mb][nb][0], acc[mb][nb][1]);
            float2 v1 = make_float2(acc[mb][nb][2], acc[mb][nb][3]);
            *(float2*)&Cg[(size_t)r * 512 + cc] = v0;
            *(float2*)&Cg[(size_t)(r + 8) * 512 + cc] = v1;
        }
    }
}

// ---------------- K2: flat-softmax column sums of the o_rel blocks ----------------
__global__ void k_relsum() {
    int d = blockIdx.x, b = blockIdx.y, side = blockIdx.z;
    const float* base = (side ? g_TI : g_TJ) + (size_t)b * 512 * 512 + d * 64;
    __shared__ float red[512];
    int tid = threadIdx.x;

    float lmax = -1e30f;
    for (int i = tid; i < 512 * 64; i += 512) {
        int h = i >> 6, p = i & 63;
        lmax = fmaxf(lmax, base[h * 512 + p]);
    }
    red[tid] = lmax; __syncthreads();
    for (int s = 256; s > 0; s >>= 1) {
        if (tid < s) red[tid] = fmaxf(red[tid], red[tid + s]);
        __syncthreads();
    }
    float M = red[0];
    __syncthreads();

    int p = tid & 63, g = tid >> 6;
    float part = 0.f;
    for (int h = g; h < 512; h += 8) part += expf(base[h * 512 + p] - M);
    red[tid] = part; __syncthreads();
    if (tid < 64) {
        float c = 0.f;
#pragma unroll
        for (int gg = 0; gg < 8; gg++) c += red[gg * 64 + tid];
        red[tid] = c;
    }
    __syncthreads();
    if (tid < 32) {
        float t2 = red[tid] + red[tid + 32];
        for (int o = 16; o > 0; o >>= 1) t2 += __shfl_down_sync(0xffffffff, t2, o);
        if (tid == 0) red[256] = t2;
    }
    __syncthreads();
    float total = red[256];
    if (tid < 64)
        g_orel[(((size_t)side * B_ + b) * DEPTH_ + d) * 64 + tid] = red[tid] / total;
}

// ---------------- K3: PT = T_proj^T @ p_x?, then fused R=PT@p_rel + flat softmax ----
__global__ __launch_bounds__(128) void k_pt2(const float* __restrict__ pxj,
                                             const float* __restrict__ pxi,
                                             const float* __restrict__ prelj,
                                             const float* __restrict__ preli) {
    int d = blockIdx.x, b = blockIdx.y, side = blockIdx.z;
    const float* A = (side ? g_TI : g_TJ) + (size_t)b * 512 * 512 + 256 + d * 64; // A[k][m]
    const float* Bw = (side ? pxi : pxj) + (size_t)d * 512 * 64;
    const float* WR = (side ? preli : prelj) + (size_t)d * 4096;
    float* C = g_PT + (((size_t)side * B_ + b) * DEPTH_ + d) * 4096;

    __shared__ __align__(16) float As[16][68];
    __shared__ __align__(16) float Bs[16][68];
    __shared__ float sPT[64][65];
    __shared__ float sWR[64][65];
    __shared__ float red[128];
    __shared__ float cs[64];

    int tid = threadIdx.x;
    int trow = tid >> 4, tcol = tid & 15;   // 8 x 16
    int mt = trow * 8, nt = tcol * 4;

    unsigned long long acc[8][2];
#pragma unroll
    for (int i = 0; i < 8; i++) { acc[i][0] = 0ull; acc[i][1] = 0ull; }

    for (int k0 = 0; k0 < 512; k0 += 16) {
        int mm = tid & 63, kb = tid >> 6;   // kb 0..1
#pragma unroll
        for (int it = 0; it < 8; it++) {
            int kk = kb + it * 2;
            As[kk][mm] = A[(k0 + kk) * 512 + mm];
            Bs[kk][mm] = Bw[(k0 + kk) * 64 + mm];
        }
        __syncthreads();
#pragma unroll
        for (int k = 0; k < 16; k++) {
            float4 a0 = *(const float4*)&As[k][mt];
            float4 a1 = *(const float4*)&As[k][mt + 4];
            ulonglong2 bq = *(const ulonglong2*)&Bs[k][nt];
            float a[8] = {a0.x, a0.y, a0.z, a0.w, a1.x, a1.y, a1.z, a1.w};
#pragma unroll
            for (int i = 0; i < 8; i++) {
                unsigned long long a2 = pack2(a[i]);
                ffma2(acc[i][0], a2, bq.x);
                ffma2(acc[i][1], a2, bq.y);
            }
        }
        __syncthreads();
    }
    // store PT to gmem + smem
#pragma unroll
    for (int i = 0; i < 8; i++) {
        *(unsigned long long*)&C[(mt + i) * 64 + nt + 0] = acc[i][0];
        *(unsigned long long*)&C[(mt + i) * 64 + nt + 2] = acc[i][1];
        sPT[mt + i][nt + 0] = __uint_as_float((unsigned)acc[i][0]);
        sPT[mt + i][nt + 1] = __uint_as_float((unsigned)(acc[i][0] >> 32));
        sPT[mt + i][nt + 2] = __uint_as_float((unsigned)acc[i][1]);
        sPT[mt + i][nt + 3] = __uint_as_float((unsigned)(acc[i][1] >> 32));
    }
    for (int i = tid; i < 4096; i += 128) sWR[i >> 6][i & 63] = WR[i];
    __syncthreads();

    // R = sPT @ sWR, flat softmax colsum
    int q = tid & 63, ih = tid >> 6;   // ih: 0/1, rows [ih*32, ih*32+32)
    float r32[32];
#pragma unroll
    for (int i = 0; i < 32; i++) r32[i] = 0.f;
    for (int k = 0; k < 64; k++) {
        float w = sWR[k][q];
#pragma unroll
        for (int i = 0; i < 32; i++) r32[i] += sPT[ih * 32 + i][k] * w;
    }
    float lm = -1e30f;
#pragma unroll
    for (int i = 0; i < 32; i++) lm = fmaxf(lm, r32[i]);
    red[tid] = lm; __syncthreads();
    for (int s = 64; s > 0; s >>= 1) {
        if (tid < s) red[tid] = fmaxf(red[tid], red[tid + s]);
        __syncthreads();
    }
    float M = red[0];
    __syncthreads();
    float s = 0.f;
#pragma unroll
    for (int i = 0; i < 32; i++) s += expf(r32[i] - M);
    red[tid] = s; __syncthreads();
    if (tid < 64) cs[tid] = red[tid] + red[tid + 64];
    __syncthreads();
    if (tid < 32) {
        float t2 = cs[tid] + cs[tid + 32];
        for (int o = 16; o > 0; o >>= 1) t2 += __shfl_down_sync(0xffffffff, t2, o);
        if (tid == 0) red[0] = t2;
    }
    __syncthreads();
    float total = red[0];
    if (tid < 64)
        g_prs[(((size_t)side * B_ + b) * DEPTH_ + d) * 64 + tid] = cs[tid] / total;
}

// ---------------- K4: per-batch epilogue: f factors, x_buf, renorm, depth-sum ----
__global__ void k_final(float* __restrict__ out) {
    int b = blockIdx.x;
    int tid = threadIdx.x;   // 256
    __shared__ float red[256];
    __shared__ float fj[64], fi[64];

    float xm = g_stats[b * 2 + 0];
    float xs = g_stats[b * 2 + 1];
    float acc[16];
#pragma unroll
    for (int r = 0; r < 16; r++) acc[r] = 0.f;

    for (int d = 0; d < DEPTH_; d++) {
        if (tid < 64) {
            size_t oj = (((size_t)0 * B_ + b) * DEPTH_ + d) * 64 + tid;
            size_t oi = (((size_t)1 * B_ + b) * DEPTH_ + d) * 64 + tid;
            fj[tid] = sqrtf(g_orel[oj] / g_prs[oj]);
            fi[tid] = sqrtf(g_orel[oi] / g_prs[oi]);
        }
        __syncthreads();

        const float* PTj = g_PT + (((size_t)0 * B_ + b) * DEPTH_ + d) * 4096;
        const float* PTi = g_PT + (((size_t)1 * B_ + b) * DEPTH_ + d) * 4096;
        float v[16], lsum = 0.f, lss = 0.f;
#pragma unroll
        for (int r = 0; r < 16; r++) {
            int e = tid + 256 * r;
            int i = e >> 6, q = e & 63;
            float vv = PTj[i * 64 + q] * fj[i] + PTi[q * 64 + i] * fi[q];
            v[r] = vv; lsum += vv; lss += vv * vv;
        }
        red[tid] = lsum; __syncthreads();
        for (int s2 = 128; s2 > 0; s2 >>= 1) {
            if (tid < s2) red[tid] += red[tid + s2];
            __syncthreads();
        }
        float mean = red[0] / 4096.f;
        __syncthreads();
        red[tid] = lss; __syncthreads();
        for (int s2 = 128; s2 > 0; s2 >>= 1) {
            if (tid < s2) red[tid] += red[tid + s2];
            __syncthreads();
        }
        float var = (red[0] - 4096.f * mean * mean) / 4095.f;
        __syncthreads();
        float inv = xs / (sqrtf(var) + EPS_);
#pragma unroll
        for (int r = 0; r < 16; r++) acc[r] += (v[r] - mean) * inv + xm;
    }
#pragma unroll
    for (int r = 0; r < 16; r++) out[(size_t)b * 4096 + tid + 256 * r] = acc[r];
}

// ---------------- launch ----------------
extern "C" void kernel_launch(void* const* d_in, const int* in_sizes, int n_in,
                              void* d_out, int out_size) {
    const float* x        = (const float*)d_in[0];
    const float* o_xj     = (const float*)d_in[1];
    const float* o_xi     = (const float*)d_in[2];
    const float* p_xj     = (const float*)d_in[3];
    const float* p_xi     = (const float*)d_in[4];
    const float* o_rel_xj = (const float*)d_in[5];
    const float* o_rel_xi = (const float*)d_in[6];
    const float* p_rel_xj = (const float*)d_in[7];
    const float* p_rel_xi = (const float*)d_in[8];
    float* out = (float*)d_out;

    // not a stream op; safe under graph capture, deterministic every call
    cudaFuncSetAttribute(k_bigmm_wm, cudaFuncAttributeMaxDynamicSharedMemorySize, SMEM_GEMM);

    k_prep<<<1024, 512>>>(o_xj, o_xi, o_rel_xj, o_rel_xi);
    k_conv<<<dim3(16, 16, B_), dim3(32, 8)>>>(x);
    k_stats<<<B_, 256>>>(x);
    k_bigmm_wm<<<dim3(4, 4, B_ * 2), 256, SMEM_GEMM>>>();
    k_relsum<<<dim3(DEPTH_, B_, 2), 512>>>();
    k_pt2<<<dim3(DEPTH_, B_, 2), 128>>>(p_xj, p_xi, p_rel_xj, p_rel_xi);
    k_final<<<B_, 256>>>(out);
}

// round 13
// speedup vs baseline: 4.3662x; 1.2289x over previous
#include <cuda_runtime.h>
#include <cuda_bf16.h>
#include <math.h>

#define B_    128
#define H_    512
#define W_    512
#define P_    64
#define DEPTH_ 4
#define EPS_  1e-5f

// ---------------- scratch (__device__ globals; no runtime allocation) ----------------
// TJ[b][h][n]: n in [0,256) = x @ o_rel_xj (d*64+p), n in [256,512) = x @ o_xj
// TI[b][w][n]: same with xt @ o_rel_xi / o_xi
__device__ __align__(16) float g_TJ[(size_t)B_ * 512 * 512];
__device__ __align__(16) float g_TI[(size_t)B_ * 512 * 512];
__device__ __align__(16) __nv_bfloat16 g_xh[(size_t)B_ * 512 * 512];   // x hi
__device__ __align__(16) __nv_bfloat16 g_xl[(size_t)B_ * 512 * 512];   // x lo
__device__ __align__(16) __nv_bfloat16 g_xth[(size_t)B_ * 512 * 512];  // x^T hi
__device__ __align__(16) __nv_bfloat16 g_xtl[(size_t)B_ * 512 * 512];  // x^T lo
__device__ __align__(16) __nv_bfloat16 g_WTh[2][512 * 512];            // W^T hi [side][n][k]
__device__ __align__(16) __nv_bfloat16 g_WTl[2][512 * 512];            // W^T lo
__device__ float g_PT[(size_t)2 * B_ * DEPTH_ * 64 * 64];  // [side][b][d][p][q]
__device__ float g_orel[(size_t)2 * B_ * DEPTH_ * 64];     // [side][b][d][p] normalized
__device__ float g_prs[(size_t)2 * B_ * DEPTH_ * 64];      // p_rel colsums, normalized
__device__ float g_stats[B_ * 2];                          // mean*scale, std*scale

// ---------------- small helpers ----------------
__device__ __forceinline__ unsigned long long pack2(float x) {
    unsigned long long r;
    asm("mov.b64 %0, {%1, %1};" : "=l"(r) : "f"(x));
    return r;
}
__device__ __forceinline__ void ffma2(unsigned long long &acc, unsigned long long a,
                                      unsigned long long b) {
    asm("fma.rn.f32x2 %0, %1, %2, %0;" : "+l"(acc) : "l"(a), "l"(b));
}
__device__ __forceinline__ unsigned smem_u32(const void* p) {
    unsigned a;
    asm("{ .reg .u64 t; cvta.to.shared.u64 t, %1; cvt.u32.u64 %0, t; }" : "=r"(a) : "l"(p));
    return a;
}
__device__ __forceinline__ void cpa16(unsigned saddr, const void* g) {
    asm volatile("cp.async.cg.shared.global [%0], [%1], 16;"
                 :: "r"(saddr), "l"(g) : "memory");
}
__device__ __forceinline__ void ldsm4(unsigned* r, unsigned addr) {
    asm volatile("ldmatrix.sync.aligned.m8n8.x4.shared.b16 {%0,%1,%2,%3}, [%4];"
                 : "=r"(r[0]), "=r"(r[1]), "=r"(r[2]), "=r"(r[3]) : "r"(addr));
}
__device__ __forceinline__ void mma16816(float* d, const unsigned* a, const unsigned* b) {
    asm volatile(
        "mma.sync.aligned.m16n8k16.row.col.f32.bf16.bf16.f32 "
        "{%0,%1,%2,%3}, {%4,%5,%6,%7}, {%8,%9}, {%0,%1,%2,%3};"
        : "+f"(d[0]), "+f"(d[1]), "+f"(d[2]), "+f"(d[3])
        : "r"(a[0]), "r"(a[1]), "r"(a[2]), "r"(a[3]), "r"(b[0]), "r"(b[1]));
}
__device__ __forceinline__ unsigned swz(int row, int colb) {
    return (unsigned)(row * 128 + (colb ^ ((row & 7) << 4)));
}

// ---------------- K0a: assemble combined transposed bf16 hi/lo weights ----------------
__global__ void k_prep(const float* __restrict__ o_xj, const float* __restrict__ o_xi,
                       const float* __restrict__ orel_xj, const float* __restrict__ orel_xi) {
    int idx = blockIdx.x * blockDim.x + threadIdx.x;   // 0 .. 2*262144-1
    int which = idx >> 18;
    int e = idx & 262143;
    int n = e >> 9, k = e & 511;
    int rel = (n < 256);
    int d = (n & 255) >> 6;
    int p = n & 63;
    const float* src = (which == 0) ? (rel ? orel_xj : o_xj) : (rel ? orel_xi : o_xi);
    float v = src[(d * 512 + k) * 64 + p];
    __nv_bfloat16 h = __float2bfloat16(v);
    g_WTh[which][n * 512 + k] = h;
    g_WTl[which][n * 512 + k] = __float2bfloat16(v - __bfloat162float(h));
}

// ---------------- K0b: convert x -> bf16 hi/lo, plus transposed copies ----------------
__global__ void k_conv(const float* __restrict__ x) {
    int b = blockIdx.z;
    int h0 = blockIdx.y * 32, w0 = blockIdx.x * 32;
    __shared__ float t[32][33];
    int tx = threadIdx.x, ty = threadIdx.y;  // 32 x 8
    const float* xb = x + (size_t)b * 262144;
    size_t ob = (size_t)b * 262144;
#pragma unroll
    for (int i = 0; i < 4; i++) {
        int r = ty + i * 8;
        float v = xb[(size_t)(h0 + r) * 512 + w0 + tx];
        t[r][tx] = v;
        __nv_bfloat16 hh = __float2bfloat16(v);
        size_t o = ob + (size_t)(h0 + r) * 512 + w0 + tx;
        g_xh[o] = hh;
        g_xl[o] = __float2bfloat16(v - __bfloat162float(hh));
    }
    __syncthreads();
#pragma unroll
    for (int i = 0; i < 4; i++) {
        int r = ty + i * 8;
        float v = t[tx][r];  // x[h0+tx][w0+r]
        __nv_bfloat16 hh = __float2bfloat16(v);
        size_t o = ob + (size_t)(w0 + r) * 512 + h0 + tx;
        g_xth[o] = hh;
        g_xtl[o] = __float2bfloat16(v - __bfloat162float(hh));
    }
}

// ---------------- K0c: per-batch mean/std of x (scaled) ----------------
__global__ void k_stats(const float* __restrict__ x) {
    int b = blockIdx.x, tid = threadIdx.x;
    const float* xb = x + (size_t)b * H_ * W_;
    float s = 0.f, ss = 0.f;
    for (int i = tid; i < H_ * W_; i += 256) {
        float v = xb[i];
        s += v; ss += v * v;
    }
    __shared__ float r1[256], r2[256];
    r1[tid] = s; r2[tid] = ss; __syncthreads();
    for (int st = 128; st > 0; st >>= 1) {
        if (tid < st) { r1[tid] += r1[tid + st]; r2[tid] += r2[tid + st]; }
        __syncthreads();
    }
    if (tid == 0) {
        float n = (float)(H_ * W_);
        float mean = r1[0] / n;
        float var = (r2[0] - n * mean * mean) / (n - 1.f);
        float scale = ((float)H_ / P_) * ((float)W_ / P_);   // 64
        g_stats[b * 2 + 0] = mean * scale;
        g_stats[b * 2 + 1] = sqrtf(var) * scale;
    }
}

// ================= K1a: rel-half GEMM (1 product), tile 128x128, 3-stage =================
// stage: A hi 16KB + B hi 16KB = 32KB; 3 stages = 96KB -> 2 CTAs/SM
#define RSTAGE 32768
#define SMEM_REL (3 * RSTAGE)

__device__ __forceinline__ void cp_rel(unsigned base,
    const __nv_bfloat16* Ah, const __nv_bfloat16* Bh, int k0, int tid)
{
#pragma unroll
    for (int i = 0; i < 4; i++) {
        int q = tid + 256 * i;
        int row = q >> 3, c = q & 7;
        unsigned o = swz(row, c * 16);
        cpa16(base + o,         (const char*)(Ah + (size_t)row * 512 + k0) + c * 16);
        cpa16(base + 16384 + o, (const char*)(Bh + (size_t)row * 512 + k0) + c * 16);
    }
    asm volatile("cp.async.commit_group;" ::: "memory");
}

__global__ __launch_bounds__(256, 2) void k_rel() {
    extern __shared__ char smem[];
    unsigned sbase = smem_u32(smem);
    int tid = threadIdx.x, lane = tid & 31, wid = tid >> 5;
    int n0 = blockIdx.x * 128, m0 = blockIdx.y * 128;
    int side = blockIdx.z & 1, b = blockIdx.z >> 1;

    const __nv_bfloat16* Ah = (side ? g_xth : g_xh) + (size_t)b * 262144 + (size_t)m0 * 512;
    const __nv_bfloat16* Bh = g_WTh[side] + (size_t)n0 * 512;
    float* Cg = (side ? g_TI : g_TJ) + (size_t)b * 262144;

    const int mw = (wid & 3) * 32;
    const int nw = (wid >> 2) * 64;

    float acc[2][8][4];
#pragma unroll
    for (int i = 0; i < 2; i++)
#pragma unroll
        for (int j = 0; j < 8; j++)
#pragma unroll
            for (int k = 0; k < 4; k++) acc[i][j][k] = 0.f;

    cp_rel(sbase, Ah, Bh, 0, tid);
    cp_rel(sbase + RSTAGE, Ah, Bh, 64, tid);

    for (int c = 0; c < 8; c++) {
        if (c == 7) asm volatile("cp.async.wait_group 0;" ::: "memory");
        else        asm volatile("cp.async.wait_group 1;" ::: "memory");
        __syncthreads();
        if (c + 2 < 8) cp_rel(sbase + ((c + 2) % 3) * RSTAGE, Ah, Bh, (c + 2) * 64, tid);
        unsigned tb = sbase + (c % 3) * RSTAGE;

#pragma unroll
        for (int kk = 0; kk < 4; kk++) {
            int ko2 = kk * 32;
            unsigned ah[2][4];
#pragma unroll
            for (int mb = 0; mb < 2; mb++) {
                int row = mw + mb * 16 + (lane & 7) + ((lane >> 3) & 1) * 8;
                int colb = ko2 + ((lane >> 4) & 1) * 16;
                ldsm4(ah[mb], tb + swz(row, colb));
            }
            unsigned bh[8][2];
#pragma unroll
            for (int nb2 = 0; nb2 < 4; nb2++) {
                int mat = lane >> 3;
                int row = nw + nb2 * 16 + (lane & 7) + (mat >> 1) * 8;
                int colb = ko2 + (mat & 1) * 16;
                unsigned t[4];
                ldsm4(t, tb + 16384 + swz(row, colb));
                bh[nb2 * 2][0] = t[0]; bh[nb2 * 2][1] = t[1];
                bh[nb2 * 2 + 1][0] = t[2]; bh[nb2 * 2 + 1][1] = t[3];
            }
#pragma unroll
            for (int mb = 0; mb < 2; mb++)
#pragma unroll
                for (int nb = 0; nb < 8; nb++)
                    mma16816(acc[mb][nb], ah[mb], bh[nb]);
        }
        __syncthreads();
    }

#pragma unroll
    for (int mb = 0; mb < 2; mb++) {
        int r = m0 + mw + mb * 16 + (lane >> 2);
#pragma unroll
        for (int nb = 0; nb < 8; nb++) {
            int cc = n0 + nw + nb * 8 + (lane & 3) * 2;
            *(float2*)&Cg[(size_t)r * 512 + cc] = make_float2(acc[mb][nb][0], acc[mb][nb][1]);
            *(float2*)&Cg[(size_t)(r + 8) * 512 + cc] = make_float2(acc[mb][nb][2], acc[mb][nb][3]);
        }
    }
}

// ================= K1b: proj-half GEMM (3 products), tile 128x64, 2-stage =================
// stage: A hi/lo 16+16KB + B hi/lo 8+8KB = 48KB; 2 stages = 96KB -> 2 CTAs/SM
#define PAH 0
#define PAL 16384
#define PBH 32768
#define PBL 40960
#define PSTAGE 49152
#define SMEM_PROJ (2 * PSTAGE)

__device__ __forceinline__ void cp_proj(unsigned base,
    const __nv_bfloat16* Ah, const __nv_bfloat16* Al,
    const __nv_bfloat16* Bh, const __nv_bfloat16* Bl, int k0, int tid)
{
#pragma unroll
    for (int i = 0; i < 4; i++) {           // A: 128 rows x 8 chunks
        int q = tid + 256 * i;
        int row = q >> 3, c = q & 7;
        unsigned o = swz(row, c * 16);
        cpa16(base + PAH + o, (const char*)(Ah + (size_t)row * 512 + k0) + c * 16);
        cpa16(base + PAL + o, (const char*)(Al + (size_t)row * 512 + k0) + c * 16);
    }
#pragma unroll
    for (int i = 0; i < 2; i++) {           // B: 64 rows x 8 chunks
        int q = tid + 256 * i;
        int row = q >> 3, c = q & 7;
        unsigned o = swz(row, c * 16);
        cpa16(base + PBH + o, (const char*)(Bh + (size_t)row * 512 + k0) + c * 16);
        cpa16(base + PBL + o, (const char*)(Bl + (size_t)row * 512 + k0) + c * 16);
    }
    asm volatile("cp.async.commit_group;" ::: "memory");
}

__global__ __launch_bounds__(256, 2) void k_proj() {
    extern __shared__ char smem[];
    unsigned sbase = smem_u32(smem);
    int tid = threadIdx.x, lane = tid & 31, wid = tid >> 5;
    int n0 = 256 + blockIdx.x * 64, m0 = blockIdx.y * 128;
    int side = blockIdx.z & 1, b = blockIdx.z >> 1;

    const __nv_bfloat16* Ah = (side ? g_xth : g_xh) + (size_t)b * 262144 + (size_t)m0 * 512;
    const __nv_bfloat16* Al = (side ? g_xtl : g_xl) + (size_t)b * 262144 + (size_t)m0 * 512;
    const __nv_bfloat16* Bh = g_WTh[side] + (size_t)n0 * 512;
    const __nv_bfloat16* Bl = g_WTl[side] + (size_t)n0 * 512;
    float* Cg = (side ? g_TI : g_TJ) + (size_t)b * 262144;

    const int mw = (wid & 3) * 32;
    const int nw = (wid >> 2) * 32;

    float acc[2][4][4];
#pragma unroll
    for (int i = 0; i < 2; i++)
#pragma unroll
        for (int j = 0; j < 4; j++)
#pragma unroll
            for (int k = 0; k < 4; k++) acc[i][j][k] = 0.f;

    cp_proj(sbase, Ah, Al, Bh, Bl, 0, tid);

    for (int c = 0; c < 8; c++) {
        asm volatile("cp.async.wait_group 0;" ::: "memory");
        __syncthreads();
        if (c < 7) cp_proj(sbase + ((c + 1) & 1) * PSTAGE, Ah, Al, Bh, Bl, (c + 1) * 64, tid);
        unsigned tb = sbase + (c & 1) * PSTAGE;

#pragma unroll
        for (int kk = 0; kk < 4; kk++) {
            int ko2 = kk * 32;
            unsigned ah[2][4], al[2][4];
#pragma unroll
            for (int mb = 0; mb < 2; mb++) {
                int row = mw + mb * 16 + (lane & 7) + ((lane >> 3) & 1) * 8;
                int colb = ko2 + ((lane >> 4) & 1) * 16;
                unsigned ad = tb + PAH + swz(row, colb);
                ldsm4(ah[mb], ad);
                ldsm4(al[mb], ad + (PAL - PAH));
            }
            unsigned bh[4][2], bl[4][2];
#pragma unroll
            for (int nb2 = 0; nb2 < 2; nb2++) {
                int mat = lane >> 3;
                int row = nw + nb2 * 16 + (lane & 7) + (mat >> 1) * 8;
                int colb = ko2 + (mat & 1) * 16;
                unsigned bd = tb + PBH + swz(row, colb);
                unsigned t[4];
                ldsm4(t, bd);
                bh[nb2 * 2][0] = t[0]; bh[nb2 * 2][1] = t[1];
                bh[nb2 * 2 + 1][0] = t[2]; bh[nb2 * 2 + 1][1] = t[3];
                ldsm4(t, bd + (PBL - PBH));
                bl[nb2 * 2][0] = t[0]; bl[nb2 * 2][1] = t[1];
                bl[nb2 * 2 + 1][0] = t[2]; bl[nb2 * 2 + 1][1] = t[3];
            }
#pragma unroll
            for (int mb = 0; mb < 2; mb++)
#pragma unroll
                for (int nb = 0; nb < 4; nb++) {
                    mma16816(acc[mb][nb], ah[mb], bh[nb]);
                    mma16816(acc[mb][nb], ah[mb], bl[nb]);
                    mma16816(acc[mb][nb], al[mb], bh[nb]);
                }
        }
        __syncthreads();
    }

#pragma unroll
    for (int mb = 0; mb < 2; mb++) {
        int r = m0 + mw + mb * 16 + (lane >> 2);
#pragma unroll
        for (int nb = 0; nb < 4; nb++) {
            int cc = n0 + nw + nb * 8 + (lane & 3) * 2;
            *(float2*)&Cg[(size_t)r * 512 + cc] = make_float2(acc[mb][nb][0], acc[mb][nb][1]);
            *(float2*)&Cg[(size_t)(r + 8) * 512 + cc] = make_float2(acc[mb][nb][2], acc[mb][nb][3]);
        }
    }
}

// ---------------- K2: flat-softmax column sums of the o_rel blocks (single pass) ----
// logits are O(10) here, so exp() without max-subtraction is safe in fp32; the
// softmax ratio is mathematically unchanged.
__global__ void k_relsum() {
    int d = blockIdx.x, b = blockIdx.y, side = blockIdx.z;
    const float* base = (side ? g_TI : g_TJ) + (size_t)b * 512 * 512 + d * 64;
    __shared__ float red[512];
    __shared__ float tot;
    int tid = threadIdx.x;

    int p = tid & 63, g = tid >> 6;
    float part = 0.f;
    for (int h = g; h < 512; h += 8) part += expf(base[h * 512 + p]);
    red[tid] = part; __syncthreads();
    if (tid < 64) {
        float c = 0.f;
#pragma unroll
        for (int gg = 0; gg < 8; gg++) c += red[gg * 64 + tid];
        red[tid] = c;
    }
    __syncthreads();
    if (tid < 32) {
        float t2 = red[tid] + red[tid + 32];
        for (int o = 16; o > 0; o >>= 1) t2 += __shfl_down_sync(0xffffffff, t2, o);
        if (tid == 0) tot = t2;
    }
    __syncthreads();
    if (tid < 64)
        g_orel[(((size_t)side * B_ + b) * DEPTH_ + d) * 64 + tid] = red[tid] / tot;
}

// ---------------- K3: PT = T_proj^T @ p_x?, then fused R=PT@p_rel + flat softmax ----
__global__ __launch_bounds__(128) void k_pt2(const float* __restrict__ pxj,
                                             const float* __restrict__ pxi,
                                             const float* __restrict__ prelj,
                                             const float* __restrict__ preli) {
    int d = blockIdx.x, b = blockIdx.y, side = blockIdx.z;
    const float* A = (side ? g_TI : g_TJ) + (size_t)b * 512 * 512 + 256 + d * 64; // A[k][m]
    const float* Bw = (side ? pxi : pxj) + (size_t)d * 512 * 64;
    const float* WR = (side ? preli : prelj) + (size_t)d * 4096;
    float* C = g_PT + (((size_t)side * B_ + b) * DEPTH_ + d) * 4096;

    __shared__ __align__(16) float As[16][68];
    __shared__ __align__(16) float Bs[16][68];
    __shared__ float sPT[64][65];
    __shared__ float sWR[64][65];
    __shared__ float red[128];
    __shared__ float cs[64];
    __shared__ float tot;

    int tid = threadIdx.x;
    int trow = tid >> 4, tcol = tid & 15;   // 8 x 16
    int mt = trow * 8, nt = tcol * 4;

    unsigned long long acc[8][2];
#pragma unroll
    for (int i = 0; i < 8; i++) { acc[i][0] = 0ull; acc[i][1] = 0ull; }

    for (int k0 = 0; k0 < 512; k0 += 16) {
        int mm = tid & 63, kb = tid >> 6;   // kb 0..1
#pragma unroll
        for (int it = 0; it < 8; it++) {
            int kk = kb + it * 2;
            As[kk][mm] = A[(k0 + kk) * 512 + mm];
            Bs[kk][mm] = Bw[(k0 + kk) * 64 + mm];
        }
        __syncthreads();
#pragma unroll
        for (int k = 0; k < 16; k++) {
            float4 a0 = *(const float4*)&As[k][mt];
            float4 a1 = *(const float4*)&As[k][mt + 4];
            ulonglong2 bq = *(const ulonglong2*)&Bs[k][nt];
            float a[8] = {a0.x, a0.y, a0.z, a0.w, a1.x, a1.y, a1.z, a1.w};
#pragma unroll
            for (int i = 0; i < 8; i++) {
                unsigned long long a2 = pack2(a[i]);
                ffma2(acc[i][0], a2, bq.x);
                ffma2(acc[i][1], a2, bq.y);
            }
        }
        __syncthreads();
    }
    // store PT to gmem + smem
#pragma unroll
    for (int i = 0; i < 8; i++) {
        *(unsigned long long*)&C[(mt + i) * 64 + nt + 0] = acc[i][0];
        *(unsigned long long*)&C[(mt + i) * 64 + nt + 2] = acc[i][1];
        sPT[mt + i][nt + 0] = __uint_as_float((unsigned)acc[i][0]);
        sPT[mt + i][nt + 1] = __uint_as_float((unsigned)(acc[i][0] >> 32));
        sPT[mt + i][nt + 2] = __uint_as_float((unsigned)acc[i][1]);
        sPT[mt + i][nt + 3] = __uint_as_float((unsigned)(acc[i][1] >> 32));
    }
    for (int i = tid; i < 4096; i += 128) sWR[i >> 6][i & 63] = WR[i];
    __syncthreads();

    // R = sPT @ sWR, flat softmax colsum (single pass, bounded logits)
    int q = tid & 63, ih = tid >> 6;   // ih: 0/1, rows [ih*32, ih*32+32)
    float r32[32];
#pragma unroll
    for (int i = 0; i < 32; i++) r32[i] = 0.f;
    for (int k = 0; k < 64; k++) {
        float w = sWR[k][q];
#pragma unroll
        for (int i = 0; i < 32; i++) r32[i] += sPT[ih * 32 + i][k] * w;
    }
    float s = 0.f;
#pragma unroll
    for (int i = 0; i < 32; i++) s += expf(r32[i]);
    red[tid] = s; __syncthreads();
    if (tid < 64) cs[tid] = red[tid] + red[tid + 64];
    __syncthreads();
    if (tid < 32) {
        float t2 = cs[tid] + cs[tid + 32];
        for (int o = 16; o > 0; o >>= 1) t2 += __shfl_down_sync(0xffffffff, t2, o);
        if (tid == 0) tot = t2;
    }
    __syncthreads();
    if (tid < 64)
        g_prs[(((size_t)side * B_ + b) * DEPTH_ + d) * 64 + tid] = cs[tid] / tot;
}

// ---------------- K4: per-batch epilogue: f factors, x_buf, renorm, depth-sum ----
__global__ void k_final(float* __restrict__ out) {
    int b = blockIdx.x;
    int tid = threadIdx.x;   // 256
    __shared__ float red[256];
    __shared__ float fj[64], fi[64];

    float xm = g_stats[b * 2 + 0];
    float xs = g_stats[b * 2 + 1];
    float acc[16];
#pragma unroll
    for (int r = 0; r < 16; r++) acc[r] = 0.f;

    for (int d = 0; d < DEPTH_; d++) {
        if (tid < 64) {
            size_t oj = (((size_t)0 * B_ + b) * DEPTH_ + d) * 64 + tid;
            size_t oi = (((size_t)1 * B_ + b) * DEPTH_ + d) * 64 + tid;
            fj[tid] = sqrtf(g_orel[oj] / g_prs[oj]);
            fi[tid] = sqrtf(g_orel[oi] / g_prs[oi]);
        }
        __syncthreads();

        const float* PTj = g_PT + (((size_t)0 * B_ + b) * DEPTH_ + d) * 4096;
        const float* PTi = g_PT + (((size_t)1 * B_ + b) * DEPTH_ + d) * 4096;
        float v[16], lsum = 0.f, lss = 0.f;
#pragma unroll
        for (int r = 0; r < 16; r++) {
            int e = tid + 256 * r;
            int i = e >> 6, q = e & 63;
            float vv = PTj[i * 64 + q] * fj[i] + PTi[q * 64 + i] * fi[q];
            v[r] = vv; lsum += vv; lss += vv * vv;
        }
        red[tid] = lsum; __syncthreads();
        for (int s2 = 128; s2 > 0; s2 >>= 1) {
            if (tid < s2) red[tid] += red[tid + s2];
            __syncthreads();
        }
        float mean = red[0] / 4096.f;
        __syncthreads();
        red[tid] = lss; __syncthreads();
        for (int s2 = 128; s2 > 0; s2 >>= 1) {
            if (tid < s2) red[tid] += red[tid + s2];
            __syncthreads();
        }
        float var = (red[0] - 4096.f * mean * mean) / 4095.f;
        __syncthreads();
        float inv = xs / (sqrtf(var) + EPS_);
#pragma unroll
        for (int r = 0; r < 16; r++) acc[r] += (v[r] - mean) * inv + xm;
    }
#pragma unroll
    for (int r = 0; r < 16; r++) out[(size_t)b * 4096 + tid + 256 * r] = acc[r];
}

// ---------------- launch ----------------
extern "C" void kernel_launch(void* const* d_in, const int* in_sizes, int n_in,
                              void* d_out, int out_size) {
    const float* x        = (const float*)d_in[0];
    const float* o_xj     = (const float*)d_in[1];
    const float* o_xi     = (const float*)d_in[2];
    const float* p_xj     = (const float*)d_in[3];
    const float* p_xi     = (const float*)d_in[4];
    const float* o_rel_xj = (const float*)d_in[5];
    const float* o_rel_xi = (const float*)d_in[6];
    const float* p_rel_xj = (const float*)d_in[7];
    const float* p_rel_xi = (const float*)d_in[8];
    float* out = (float*)d_out;

    // not stream ops; safe under graph capture, deterministic every call
    cudaFuncSetAttribute(k_rel,  cudaFuncAttributeMaxDynamicSharedMemorySize, SMEM_REL);
    cudaFuncSetAttribute(k_proj, cudaFuncAttributeMaxDynamicSharedMemorySize, SMEM_PROJ);

    k_prep<<<1024, 512>>>(o_xj, o_xi, o_rel_xj, o_rel_xi);
    k_conv<<<dim3(16, 16, B_), dim3(32, 8)>>>(x);
    k_stats<<<B_, 256>>>(x);
    k_proj<<<dim3(4, 4, B_ * 2), 256, SMEM_PROJ>>>();
    k_rel<<<dim3(2, 4, B_ * 2), 256, SMEM_REL>>>();
    k_relsum<<<dim3(DEPTH_, B_, 2), 512>>>();
    k_pt2<<<dim3(DEPTH_, B_, 2), 128>>>(p_xj, p_xi, p_rel_xj, p_rel_xi);
    k_final<<<B_, 256>>>(out);
}